// round 8
// baseline (speedup 1.0000x reference)
#include <cuda_runtime.h>
#include <cuda_fp16.h>
#include <cstdint>

#define HEADS 8
#define SEQ   4096
#define FIN   512
#define HD    64
#define FOUT  512

// ---------------------------------------------------------------------------
// Scratch (__device__ globals: allocation-free rule)
// ---------------------------------------------------------------------------
__device__ __half g_Qh [HEADS * SEQ * HD];           // pre-scaled by 1/8
__device__ __half g_Khi[HEADS * SEQ * HD];
__device__ __half g_Klo[HEADS * SEQ * HD];
__device__ __half g_Vthi[HEADS * HD * SEQ];          // transposed: [h][d][n]
__device__ __half g_Vtlo[HEADS * HD * SEQ];
__device__ float g_Hcat[SEQ * (HEADS * HD)];

// ---------------------------------------------------------------------------
// Helpers
// ---------------------------------------------------------------------------
__device__ __forceinline__ uint32_t smem_u32(const void* p) {
    uint32_t a;
    asm("{ .reg .u64 t; cvta.to.shared.u64 t, %1; cvt.u32.u64 %0, t; }"
        : "=r"(a) : "l"(p));
    return a;
}

__device__ __forceinline__ void ldsm_x4(uint32_t r[4], uint32_t addr) {
    asm volatile("ldmatrix.sync.aligned.m8n8.x4.shared.b16 {%0,%1,%2,%3}, [%4];"
                 : "=r"(r[0]), "=r"(r[1]), "=r"(r[2]), "=r"(r[3]) : "r"(addr));
}

__device__ __forceinline__ void mma_f16(float* c, const uint32_t* a, const uint32_t* b) {
    asm volatile(
        "mma.sync.aligned.m16n8k16.row.col.f32.f16.f16.f32 "
        "{%0,%1,%2,%3},{%4,%5,%6,%7},{%8,%9},{%0,%1,%2,%3};"
        : "+f"(c[0]), "+f"(c[1]), "+f"(c[2]), "+f"(c[3])
        : "r"(a[0]), "r"(a[1]), "r"(a[2]), "r"(a[3]), "r"(b[0]), "r"(b[1]));
}

__device__ __forceinline__ float ex2f(float x) {
    float y; asm("ex2.approx.f32 %0, %1;" : "=f"(y) : "f"(x)); return y;
}

// pack two floats to f16x2 (lo -> low half, hi -> high half)
__device__ __forceinline__ uint32_t pack_f16x2(float lo, float hi) {
    __half2 h = __floats2half2_rn(lo, hi);
    return *reinterpret_cast<uint32_t*>(&h);
}
__device__ __forceinline__ float2 unpack_f16x2(uint32_t w) {
    __half2 h = *reinterpret_cast<__half2*>(&w);
    return __half22float2(h);
}

__device__ __forceinline__ void cp16(uint32_t saddr, const void* g) {
    asm volatile("cp.async.cg.shared.global [%0], [%1], 16;"
                 :: "r"(saddr), "l"(g) : "memory");
}
#define CP_COMMIT() asm volatile("cp.async.commit_group;" ::: "memory")
#define CP_WAIT(n)  asm volatile("cp.async.wait_group %0;" :: "n"(n) : "memory")

__device__ __forceinline__ void write_split2(__half* ph, __half* pl,
                                             float v0, float v1) {
    uint32_t hw = pack_f16x2(v0, v1);
    float2 hf = unpack_f16x2(hw);
    uint32_t lw = pack_f16x2(v0 - hf.x, v1 - hf.y);
    *(uint32_t*)ph = hw;
    *(uint32_t*)pl = lw;
}

__device__ __forceinline__ void write_split1(__half* ph, __half* pl, float v) {
    __half hb = __float2half_rn(v);
    *ph = hb;
    *pl = __float2half_rn(v - __half2float(hb));
}

// B-side split store (hi/lo fp16), 4 values
__device__ __forceinline__ void split_store4(__half* ph, __half* pl, float4 v) {
    uint32_t h0 = pack_f16x2(v.x, v.y);
    uint32_t h1 = pack_f16x2(v.z, v.w);
    float2 f0 = unpack_f16x2(h0);
    float2 f1 = unpack_f16x2(h1);
    uint32_t l0 = pack_f16x2(v.x - f0.x, v.y - f0.y);
    uint32_t l1 = pack_f16x2(v.z - f1.x, v.w - f1.y);
    *(uint2*)ph = make_uint2(h0, h1);
    *(uint2*)pl = make_uint2(l0, l1);
}

// A-side hi-only store, 4 values
__device__ __forceinline__ void hi_store4(__half* ph, float4 v) {
    *(uint2*)ph = make_uint2(pack_f16x2(v.x, v.y), pack_f16x2(v.z, v.w));
}

// ---------------------------------------------------------------------------
// GEMM core (BM=128, BN=64, BK=32, 8 warps, warp tile 32x32)
// A hi-only fp16; B hi/lo fp16; C = A*(Bh+Bl)^T 2-term.
// ---------------------------------------------------------------------------
#define G_LDA 40

#define GEMM_PREFETCH(A_, B_, K_, k0_)                                            \
    do {                                                                          \
        _Pragma("unroll")                                                         \
        for (int it = 0; it < 4; it++) {                                          \
            int i = tid + it * 256;                                               \
            pa[it] = *(const float4*)(A_ + (long)(bm + (i >> 3)) * K_ + (k0_) + (i & 7) * 4); \
        }                                                                         \
        _Pragma("unroll")                                                         \
        for (int it = 0; it < 2; it++) {                                          \
            int i = tid + it * 256;                                               \
            pb[it] = *(const float4*)(B_ + (long)((i >> 3)) * K_ + (k0_) + (i & 7) * 4); \
        }                                                                         \
    } while (0)

#define GEMM_STORE_SMEM()                                                         \
    do {                                                                          \
        _Pragma("unroll")                                                         \
        for (int it = 0; it < 4; it++) {                                          \
            int i = tid + it * 256; int r = i >> 3, c = i & 7;                    \
            hi_store4(Ah + r * G_LDA + c * 4, pa[it]);                            \
        }                                                                         \
        _Pragma("unroll")                                                         \
        for (int it = 0; it < 2; it++) {                                          \
            int i = tid + it * 256; int r = i >> 3, c = i & 7;                    \
            split_store4(Bh + r * G_LDA + c * 4, Bl + r * G_LDA + c * 4, pb[it]); \
        }                                                                         \
    } while (0)

#define GEMM_MMA_BLOCK()                                                          \
    do {                                                                          \
        _Pragma("unroll")                                                         \
        for (int kc = 0; kc < 2; kc++) {                                          \
            uint32_t ah[2][4], bh[2][4], bl[2][4];                                \
            const int ar = wm + (lane & 15);                                      \
            const int acol = kc * 16 + ((lane >> 4) << 3);                        \
            ldsm_x4(ah[0], smem_u32(Ah + ar * G_LDA + acol));                     \
            ldsm_x4(ah[1], smem_u32(Ah + (ar + 16) * G_LDA + acol));              \
            const int brow = ((lane >> 4) << 3) + (lane & 7);                     \
            const int bcol = kc * 16 + (((lane >> 3) & 1) << 3);                  \
            ldsm_x4(bh[0], smem_u32(Bh + (wn + brow) * G_LDA + bcol));            \
            ldsm_x4(bh[1], smem_u32(Bh + (wn + 16 + brow) * G_LDA + bcol));       \
            ldsm_x4(bl[0], smem_u32(Bl + (wn + brow) * G_LDA + bcol));            \
            ldsm_x4(bl[1], smem_u32(Bl + (wn + 16 + brow) * G_LDA + bcol));       \
            _Pragma("unroll")                                                     \
            for (int mi = 0; mi < 2; mi++)                                        \
                _Pragma("unroll")                                                 \
                for (int jp = 0; jp < 2; jp++)                                    \
                    _Pragma("unroll")                                             \
                    for (int u = 0; u < 2; u++) {                                 \
                        int j = jp * 2 + u;                                       \
                        mma_f16(acc[mi][j], ah[mi], &bh[jp][2 * u]);              \
                        mma_f16(acc[mi][j], ah[mi], &bl[jp][2 * u]);              \
                    }                                                             \
        }                                                                         \
    } while (0)

// ---------------------------------------------------------------------------
// Fused Q/K/V projection: y = 0/1/2 -> Q (hi only, pre-scaled 1/8) / K / V^T
// ---------------------------------------------------------------------------
__global__ __launch_bounds__(256) void proj_qkv(
    const float* __restrict__ X,
    const float* __restrict__ W_Q, const float* __restrict__ W_K,
    const float* __restrict__ W_V,
    __half* __restrict__ Qh_g,
    __half* __restrict__ Khi, __half* __restrict__ Klo,
    __half* __restrict__ Vthi, __half* __restrict__ Vtlo)
{
    __shared__ __half Ah[128 * G_LDA];
    __shared__ __half Bh[64 * G_LDA], Bl[64 * G_LDA];

    const int tid = threadIdx.x, wid = tid >> 5, lane = tid & 31;
    const int z = blockIdx.z, y = blockIdx.y;
    const int bm = blockIdx.x * 128;
    const float* A = X + (long)z * SEQ * FIN;
    const float* B = (y == 0 ? W_Q : (y == 1 ? W_K : W_V)) + (long)z * HD * FIN;
    const int wm = (wid & 3) * 32, wn = (wid >> 2) * 32;

    float acc[2][4][4] = {};
    float4 pa[4], pb[2];
    GEMM_PREFETCH(A, B, FIN, 0);

    for (int k0 = 0; k0 < FIN; k0 += 32) {
        __syncthreads();
        GEMM_STORE_SMEM();
        __syncthreads();
        if (k0 + 32 < FIN) GEMM_PREFETCH(A, B, FIN, k0 + 32);
        GEMM_MMA_BLOCK();
    }

    #pragma unroll
    for (int mi = 0; mi < 2; mi++) {
        const int gm0 = bm + wm + mi * 16 + (lane >> 2);
        #pragma unroll
        for (int j = 0; j < 4; j++) {
            const int col = wn + j * 8 + (lane & 3) * 2;
            float v0 = acc[mi][j][0], v1 = acc[mi][j][1];
            float v2 = acc[mi][j][2], v3 = acc[mi][j][3];
            if (y == 0) {
                long b0 = ((long)z * SEQ + gm0) * HD + col;
                *(uint32_t*)(Qh_g + b0) = pack_f16x2(v0 * 0.125f, v1 * 0.125f);
                *(uint32_t*)(Qh_g + b0 + 8L * HD) = pack_f16x2(v2 * 0.125f, v3 * 0.125f);
            } else if (y == 1) {
                long b0 = ((long)z * SEQ + gm0) * HD + col;
                write_split2(Khi + b0, Klo + b0, v0, v1);
                long b1 = b0 + 8L * HD;
                write_split2(Khi + b1, Klo + b1, v2, v3);
            } else {
                long t0 = ((long)z * HD + col) * SEQ + gm0;
                write_split1(Vthi + t0, Vtlo + t0, v0);
                write_split1(Vthi + t0 + SEQ, Vtlo + t0 + SEQ, v1);
                write_split1(Vthi + t0 + 8, Vtlo + t0 + 8, v2);
                write_split1(Vthi + t0 + SEQ + 8, Vtlo + t0 + SEQ + 8, v3);
            }
        }
    }
}

// ---------------------------------------------------------------------------
// Output projection: out[4096,512] = Hcat[4096,512] * W_O[512,512]^T (fp32)
// ---------------------------------------------------------------------------
__global__ __launch_bounds__(256) void gemm_out(
    const float* __restrict__ A, const float* __restrict__ W,
    float* __restrict__ C)
{
    __shared__ __half Ah[128 * G_LDA];
    __shared__ __half Bh[64 * G_LDA], Bl[64 * G_LDA];

    const int tid = threadIdx.x, wid = tid >> 5, lane = tid & 31;
    const int bm = blockIdx.x * 128, bn = blockIdx.y * 64;
    const float* B = W + (long)bn * FIN;
    const int wm = (wid & 3) * 32, wn = (wid >> 2) * 32;

    float acc[2][4][4] = {};
    float4 pa[4], pb[2];
    GEMM_PREFETCH(A, B, FIN, 0);

    for (int k0 = 0; k0 < FIN; k0 += 32) {
        __syncthreads();
        GEMM_STORE_SMEM();
        __syncthreads();
        if (k0 + 32 < FIN) GEMM_PREFETCH(A, B, FIN, k0 + 32);
        GEMM_MMA_BLOCK();
    }

    #pragma unroll
    for (int mi = 0; mi < 2; mi++) {
        const int gm0 = bm + wm + mi * 16 + (lane >> 2);
        #pragma unroll
        for (int j = 0; j < 4; j++) {
            const int col = bn + wn + j * 8 + (lane & 3) * 2;
            *(float2*)(C + (long)gm0 * FOUT + col) =
                make_float2(acc[mi][j][0], acc[mi][j][1]);
            *(float2*)(C + (long)(gm0 + 8) * FOUT + col) =
                make_float2(acc[mi][j][2], acc[mi][j][3]);
        }
    }
}

// ---------------------------------------------------------------------------
// HMMA flash attention, fp16 2-term. BQ=64, 128 threads, 3 CTAs/SM.
// XOR-swizzled smem (no padding): phys = row*128 + ((col16 ^ (row&7))<<4).
// Q hi-only (pre-scaled), K/V hi+lo, double-buffered via cp.async.
// ---------------------------------------------------------------------------
#define HALF_A  8192                   // one 64x64 fp16 array, 128B rows
#define KV_STG  (2 * HALF_A)           // hi+lo pair per stage = 16384
#define OFF_K   HALF_A                 // after Q
#define OFF_V   (OFF_K + 2 * KV_STG)
#define ATT_SMEM (OFF_V + 2 * KV_STG)  // 73728 bytes -> 3 CTAs/SM

__global__ __launch_bounds__(128, 3) void attn_mma(
    const __half* __restrict__ Qh_g,
    const __half* __restrict__ Khi, const __half* __restrict__ Klo,
    const __half* __restrict__ Vthi, const __half* __restrict__ Vtlo,
    const int* __restrict__ mask, float* __restrict__ Hcat)
{
    extern __shared__ char smc[];
    const uint32_t sb = smem_u32(smc);

    const int tid = threadIdx.x, wid = tid >> 5, lane = tid & 31;
    const int h = blockIdx.y, q0 = blockIdx.x * 64;
    const long hS = (long)h * SEQ;

    // cp.async mapping: thread (rr, cc) covers rows rr+16k, 16B chunk cc.
    // XOR swizzle is invariant under row += 16 (rr&7 unchanged).
    const int rr = (tid >> 3) & 15;   // 0..15
    const int cc = tid & 7;
    const uint32_t swo = (uint32_t)((cc ^ (rr & 7)) << 4);
    const __half* pKh = Khi + (hS + rr) * HD + cc * 8;
    const __half* pKl = Klo + (hS + rr) * HD + cc * 8;
    const __half* pVh = Vthi + ((long)h * HD + rr) * SEQ + cc * 8;
    const __half* pVl = Vtlo + ((long)h * HD + rr) * SEQ + cc * 8;
    const uint32_t sKf = sb + OFF_K + rr * 128 + swo;
    const uint32_t sVf = sb + OFF_V + rr * 128 + swo;

#define FILL_STAGE(kt_)                                                        \
    do {                                                                       \
        uint32_t k0s = sKf + ((kt_) & 1) * KV_STG;                             \
        uint32_t v0s = sVf + ((kt_) & 1) * KV_STG;                             \
        long ko = (long)(kt_) * 64;                                            \
        _Pragma("unroll")                                                      \
        for (int kq = 0; kq < 4; kq++) {                                       \
            cp16(k0s + kq * 2048,          pKh + (ko + kq * 16) * HD);         \
            cp16(k0s + kq * 2048 + HALF_A, pKl + (ko + kq * 16) * HD);         \
            cp16(v0s + kq * 2048,          pVh + (long)kq * 16 * SEQ + ko);    \
            cp16(v0s + kq * 2048 + HALF_A, pVl + (long)kq * 16 * SEQ + ko);    \
        }                                                                      \
        CP_COMMIT();                                                           \
    } while (0)

    // Load Q tile (swizzled store), persists all iterations
    #pragma unroll
    for (int it = 0; it < 4; it++) {
        int i = tid + it * 128;
        int r = i >> 3, c = i & 7;
        uint32_t off = (uint32_t)(r * 128 + ((c ^ (r & 7)) << 4));
        *(uint4*)(smc + off) = *(const uint4*)(Qh_g + (hS + q0 + r) * HD + c * 8);
    }
    FILL_STAGE(0);
    __syncthreads();

    // Q fragments -> registers
    uint32_t qh[4][4];
    {
        const int r = wid * 16 + (lane & 15);
        #pragma unroll
        for (int kc = 0; kc < 4; kc++) {
            const int c16 = 2 * kc + (lane >> 4);
            ldsm_x4(qh[kc], sb + r * 128 + ((c16 ^ (r & 7)) << 4));
        }
    }

    float o[8][4] = {};
    float l0 = 0.f, l1 = 0.f;
    const int r0 = q0 + wid * 16 + (lane >> 2);
    const int colb = (lane & 3) * 2;
    const long mbase = (hS + r0) * SEQ;

    // ldmatrix B-side lane geometry (shared by K and V reads)
    const int brow = ((lane >> 4) << 3) + (lane & 7);   // 0..15
    const int bsw = brow & 7;

    for (int kt = 0; kt < SEQ / 64; kt++) {
        if (kt) __syncthreads();
        if (kt + 1 < SEQ / 64) { FILL_STAGE(kt + 1); CP_WAIT(1); }
        else                   { CP_WAIT(0); }
        __syncthreads();

        const uint32_t kbK = sb + OFF_K + (kt & 1) * KV_STG;
        const uint32_t kbV = sb + OFF_V + (kt & 1) * KV_STG;

        // mask loads (hidden under S chain)
        int2 mv0[8], mv1[8];
        #pragma unroll
        for (int j = 0; j < 8; j++) {
            mv0[j] = *(const int2*)(mask + mbase + kt * 64 + j * 8 + colb);
            mv1[j] = *(const int2*)(mask + mbase + 8L * SEQ + kt * 64 + j * 8 + colb);
        }

        // S = Qh * (Kh + Kl)  (2-term)
        float s[8][4] = {};
        #pragma unroll
        for (int kc = 0; kc < 4; kc++) {
            uint32_t kbh[4][4], kbl[4][4];
            const int c16 = 2 * kc + ((lane >> 3) & 1);
            const uint32_t co = (uint32_t)((c16 ^ bsw) << 4);
            #pragma unroll
            for (int jp = 0; jp < 4; jp++) {
                ldsm_x4(kbh[jp], kbK + (jp * 16 + brow) * 128 + co);
                ldsm_x4(kbl[jp], kbK + HALF_A + (jp * 16 + brow) * 128 + co);
            }
            #pragma unroll
            for (int jp = 0; jp < 4; jp++) {
                mma_f16(s[2 * jp],     qh[kc], &kbh[jp][0]);
                mma_f16(s[2 * jp],     qh[kc], &kbl[jp][0]);
                mma_f16(s[2 * jp + 1], qh[kc], &kbh[jp][2]);
                mma_f16(s[2 * jp + 1], qh[kc], &kbl[jp][2]);
            }
        }

        // mask + exp (no rescale; Q pre-scaled so s is the exponent arg)
        const float CE = 1.44269504f;   // log2(e)
        #pragma unroll
        for (int j = 0; j < 8; j++) {
            float p0 = mv0[j].x ? ex2f(s[j][0] * CE) : 0.f;
            float p1 = mv0[j].y ? ex2f(s[j][1] * CE) : 0.f;
            float p2 = mv1[j].x ? ex2f(s[j][2] * CE) : 0.f;
            float p3 = mv1[j].y ? ex2f(s[j][3] * CE) : 0.f;
            l0 += p0 + p1;
            l1 += p2 + p3;
            s[j][0] = p0; s[j][1] = p1; s[j][2] = p2; s[j][3] = p3;
        }

        // Repack P C-frags -> A-frags (hi only, fp16)
        uint32_t ph[4][4];
        #pragma unroll
        for (int kc = 0; kc < 4; kc++) {
            #pragma unroll
            for (int u = 0; u < 2; u++) {
                const int j = 2 * kc + u;
                ph[kc][2 * u]     = pack_f16x2(s[j][0], s[j][1]);
                ph[kc][2 * u + 1] = pack_f16x2(s[j][2], s[j][3]);
            }
        }

        // O += Ph * (Vh + Vl)  (2-term)
        #pragma unroll
        for (int kc = 0; kc < 4; kc++) {
            uint32_t vbh[4][4], vbl[4][4];
            const int c16 = 2 * kc + ((lane >> 3) & 1);
            const uint32_t co = (uint32_t)((c16 ^ bsw) << 4);
            #pragma unroll
            for (int jp = 0; jp < 4; jp++) {
                ldsm_x4(vbh[jp], kbV + (jp * 16 + brow) * 128 + co);
                ldsm_x4(vbl[jp], kbV + HALF_A + (jp * 16 + brow) * 128 + co);
            }
            #pragma unroll
            for (int jp = 0; jp < 4; jp++) {
                mma_f16(o[2 * jp],     ph[kc], &vbh[jp][0]);
                mma_f16(o[2 * jp],     ph[kc], &vbl[jp][0]);
                mma_f16(o[2 * jp + 1], ph[kc], &vbh[jp][2]);
                mma_f16(o[2 * jp + 1], ph[kc], &vbl[jp][2]);
            }
        }
    }

    // Row-sum reduce across the quad, normalize, write Hcat
    l0 += __shfl_xor_sync(0xffffffffu, l0, 1);
    l0 += __shfl_xor_sync(0xffffffffu, l0, 2);
    l1 += __shfl_xor_sync(0xffffffffu, l1, 1);
    l1 += __shfl_xor_sync(0xffffffffu, l1, 2);
    const float i0 = 1.f / l0, i1 = 1.f / l1;
    #pragma unroll
    for (int j = 0; j < 8; j++) {
        const int colg = h * HD + j * 8 + colb;
        *(float2*)(Hcat + (long)r0 * (HEADS * HD) + colg) =
            make_float2(o[j][0] * i0, o[j][1] * i0);
        *(float2*)(Hcat + (long)(r0 + 8) * (HEADS * HD) + colg) =
            make_float2(o[j][2] * i1, o[j][3] * i1);
    }
}

// ---------------------------------------------------------------------------
extern "C" void kernel_launch(void* const* d_in, const int* in_sizes, int n_in,
                              void* d_out, int out_size)
{
    const float* X    = (const float*)d_in[0];
    const int*   mask = (const int*)  d_in[1];
    const float* W_Q  = (const float*)d_in[2];
    const float* W_K  = (const float*)d_in[3];
    const float* W_V  = (const float*)d_in[4];
    const float* W_O  = (const float*)d_in[5];
    float* out = (float*)d_out;

    __half *Qh_g, *Khi, *Klo, *Vthi, *Vtlo;
    float* Hc;
    cudaGetSymbolAddress((void**)&Qh_g, g_Qh);
    cudaGetSymbolAddress((void**)&Khi,  g_Khi);
    cudaGetSymbolAddress((void**)&Klo,  g_Klo);
    cudaGetSymbolAddress((void**)&Vthi, g_Vthi);
    cudaGetSymbolAddress((void**)&Vtlo, g_Vtlo);
    cudaGetSymbolAddress((void**)&Hc,   g_Hcat);

    // Fused Q/K/V projections
    dim3 gProj(SEQ / 128, 3, HEADS);
    proj_qkv<<<gProj, 256>>>(X, W_Q, W_K, W_V, Qh_g, Khi, Klo, Vthi, Vtlo);

    // Attention (BQ=64, swizzled smem, 3 CTAs/SM)
    cudaFuncSetAttribute(attn_mma,
                         cudaFuncAttributeMaxDynamicSharedMemorySize, ATT_SMEM);
    dim3 gAttn(SEQ / 64, HEADS);
    attn_mma<<<gAttn, 128, ATT_SMEM>>>(Qh_g, Khi, Klo, Vthi, Vtlo, mask, Hc);

    // Output projection
    dim3 gOut(SEQ / 128, FOUT / 64);
    gemm_out<<<gOut, 256>>>(Hc, W_O, out);
}

// round 9
// speedup vs baseline: 1.2546x; 1.2546x over previous
#include <cuda_runtime.h>
#include <cuda_fp16.h>
#include <cstdint>

#define HEADS 8
#define SEQ   4096
#define FIN   512
#define HD    64
#define FOUT  512

// ---------------------------------------------------------------------------
// Scratch (__device__ globals: allocation-free rule)
// ---------------------------------------------------------------------------
__device__ __half g_Qh [HEADS * SEQ * HD];           // pre-scaled by 1/8
__device__ __half g_Khi[HEADS * SEQ * HD];
__device__ __half g_Klo[HEADS * SEQ * HD];
__device__ __half g_Vt [HEADS * HD * SEQ];           // transposed: [h][d][n], fp16
__device__ float g_Hcat[SEQ * (HEADS * HD)];

// ---------------------------------------------------------------------------
// Helpers
// ---------------------------------------------------------------------------
__device__ __forceinline__ uint32_t smem_u32(const void* p) {
    uint32_t a;
    asm("{ .reg .u64 t; cvta.to.shared.u64 t, %1; cvt.u32.u64 %0, t; }"
        : "=r"(a) : "l"(p));
    return a;
}

__device__ __forceinline__ void ldsm_x4(uint32_t r[4], uint32_t addr) {
    asm volatile("ldmatrix.sync.aligned.m8n8.x4.shared.b16 {%0,%1,%2,%3}, [%4];"
                 : "=r"(r[0]), "=r"(r[1]), "=r"(r[2]), "=r"(r[3]) : "r"(addr));
}

__device__ __forceinline__ void mma_f16(float* c, const uint32_t* a, const uint32_t* b) {
    asm volatile(
        "mma.sync.aligned.m16n8k16.row.col.f32.f16.f16.f32 "
        "{%0,%1,%2,%3},{%4,%5,%6,%7},{%8,%9},{%0,%1,%2,%3};"
        : "+f"(c[0]), "+f"(c[1]), "+f"(c[2]), "+f"(c[3])
        : "r"(a[0]), "r"(a[1]), "r"(a[2]), "r"(a[3]), "r"(b[0]), "r"(b[1]));
}

__device__ __forceinline__ float ex2f(float x) {
    float y; asm("ex2.approx.f32 %0, %1;" : "=f"(y) : "f"(x)); return y;
}

__device__ __forceinline__ uint32_t pack_f16x2(float lo, float hi) {
    __half2 h = __floats2half2_rn(lo, hi);
    return *reinterpret_cast<uint32_t*>(&h);
}
__device__ __forceinline__ float2 unpack_f16x2(uint32_t w) {
    __half2 h = *reinterpret_cast<__half2*>(&w);
    return __half22float2(h);
}

__device__ __forceinline__ void cp16(uint32_t saddr, const void* g) {
    asm volatile("cp.async.cg.shared.global [%0], [%1], 16;"
                 :: "r"(saddr), "l"(g) : "memory");
}
#define CP_COMMIT() asm volatile("cp.async.commit_group;" ::: "memory")
#define CP_WAIT(n)  asm volatile("cp.async.wait_group %0;" :: "n"(n) : "memory")

// streaming (evict-first) int2 load for the one-pass mask stream
__device__ __forceinline__ int2 ldcs2(const int* p) {
    int2 v;
    asm volatile("ld.global.cs.v2.s32 {%0,%1}, [%2];"
                 : "=r"(v.x), "=r"(v.y) : "l"(p));
    return v;
}

__device__ __forceinline__ void write_split2(__half* ph, __half* pl,
                                             float v0, float v1) {
    uint32_t hw = pack_f16x2(v0, v1);
    float2 hf = unpack_f16x2(hw);
    uint32_t lw = pack_f16x2(v0 - hf.x, v1 - hf.y);
    *(uint32_t*)ph = hw;
    *(uint32_t*)pl = lw;
}

// B-side split store (hi/lo fp16), 4 values
__device__ __forceinline__ void split_store4(__half* ph, __half* pl, float4 v) {
    uint32_t h0 = pack_f16x2(v.x, v.y);
    uint32_t h1 = pack_f16x2(v.z, v.w);
    float2 f0 = unpack_f16x2(h0);
    float2 f1 = unpack_f16x2(h1);
    uint32_t l0 = pack_f16x2(v.x - f0.x, v.y - f0.y);
    uint32_t l1 = pack_f16x2(v.z - f1.x, v.w - f1.y);
    *(uint2*)ph = make_uint2(h0, h1);
    *(uint2*)pl = make_uint2(l0, l1);
}

// A-side hi-only store, 4 values
__device__ __forceinline__ void hi_store4(__half* ph, float4 v) {
    *(uint2*)ph = make_uint2(pack_f16x2(v.x, v.y), pack_f16x2(v.z, v.w));
}

// ---------------------------------------------------------------------------
// GEMM core (BM=128, BN=64, BK=32, 8 warps, warp tile 32x32)
// A hi-only fp16; B hi/lo fp16; C = A*(Bh+Bl)^T 2-term.
// ---------------------------------------------------------------------------
#define G_LDA 40

#define GEMM_PREFETCH(A_, B_, K_, k0_)                                            \
    do {                                                                          \
        _Pragma("unroll")                                                         \
        for (int it = 0; it < 4; it++) {                                          \
            int i = tid + it * 256;                                               \
            pa[it] = *(const float4*)(A_ + (long)(bm + (i >> 3)) * K_ + (k0_) + (i & 7) * 4); \
        }                                                                         \
        _Pragma("unroll")                                                         \
        for (int it = 0; it < 2; it++) {                                          \
            int i = tid + it * 256;                                               \
            pb[it] = *(const float4*)(B_ + (long)((i >> 3)) * K_ + (k0_) + (i & 7) * 4); \
        }                                                                         \
    } while (0)

#define GEMM_STORE_SMEM()                                                         \
    do {                                                                          \
        _Pragma("unroll")                                                         \
        for (int it = 0; it < 4; it++) {                                          \
            int i = tid + it * 256; int r = i >> 3, c = i & 7;                    \
            hi_store4(Ah + r * G_LDA + c * 4, pa[it]);                            \
        }                                                                         \
        _Pragma("unroll")                                                         \
        for (int it = 0; it < 2; it++) {                                          \
            int i = tid + it * 256; int r = i >> 3, c = i & 7;                    \
            split_store4(Bh + r * G_LDA + c * 4, Bl + r * G_LDA + c * 4, pb[it]); \
        }                                                                         \
    } while (0)

#define GEMM_MMA_BLOCK()                                                          \
    do {                                                                          \
        _Pragma("unroll")                                                         \
        for (int kc = 0; kc < 2; kc++) {                                          \
            uint32_t ah[2][4], bh[2][4], bl[2][4];                                \
            const int ar = wm + (lane & 15);                                      \
            const int acol = kc * 16 + ((lane >> 4) << 3);                        \
            ldsm_x4(ah[0], smem_u32(Ah + ar * G_LDA + acol));                     \
            ldsm_x4(ah[1], smem_u32(Ah + (ar + 16) * G_LDA + acol));              \
            const int brow = ((lane >> 4) << 3) + (lane & 7);                     \
            const int bcol = kc * 16 + (((lane >> 3) & 1) << 3);                  \
            ldsm_x4(bh[0], smem_u32(Bh + (wn + brow) * G_LDA + bcol));            \
            ldsm_x4(bh[1], smem_u32(Bh + (wn + 16 + brow) * G_LDA + bcol));       \
            ldsm_x4(bl[0], smem_u32(Bl + (wn + brow) * G_LDA + bcol));            \
            ldsm_x4(bl[1], smem_u32(Bl + (wn + 16 + brow) * G_LDA + bcol));       \
            _Pragma("unroll")                                                     \
            for (int mi = 0; mi < 2; mi++)                                        \
                _Pragma("unroll")                                                 \
                for (int jp = 0; jp < 2; jp++)                                    \
                    _Pragma("unroll")                                             \
                    for (int u = 0; u < 2; u++) {                                 \
                        int j = jp * 2 + u;                                       \
                        mma_f16(acc[mi][j], ah[mi], &bh[jp][2 * u]);              \
                        mma_f16(acc[mi][j], ah[mi], &bl[jp][2 * u]);              \
                    }                                                             \
        }                                                                         \
    } while (0)

// ---------------------------------------------------------------------------
// Fused Q/K/V projection: y = 0/1/2 -> Q (hi only, pre-scaled 1/8) / K / V^T
// ---------------------------------------------------------------------------
__global__ __launch_bounds__(256) void proj_qkv(
    const float* __restrict__ X,
    const float* __restrict__ W_Q, const float* __restrict__ W_K,
    const float* __restrict__ W_V,
    __half* __restrict__ Qh_g,
    __half* __restrict__ Khi, __half* __restrict__ Klo,
    __half* __restrict__ Vt)
{
    __shared__ __half Ah[128 * G_LDA];
    __shared__ __half Bh[64 * G_LDA], Bl[64 * G_LDA];

    const int tid = threadIdx.x, wid = tid >> 5, lane = tid & 31;
    const int z = blockIdx.z, y = blockIdx.y;
    const int bm = blockIdx.x * 128;
    const float* A = X + (long)z * SEQ * FIN;
    const float* B = (y == 0 ? W_Q : (y == 1 ? W_K : W_V)) + (long)z * HD * FIN;
    const int wm = (wid & 3) * 32, wn = (wid >> 2) * 32;

    float acc[2][4][4] = {};
    float4 pa[4], pb[2];
    GEMM_PREFETCH(A, B, FIN, 0);

    for (int k0 = 0; k0 < FIN; k0 += 32) {
        __syncthreads();
        GEMM_STORE_SMEM();
        __syncthreads();
        if (k0 + 32 < FIN) GEMM_PREFETCH(A, B, FIN, k0 + 32);
        GEMM_MMA_BLOCK();
    }

    #pragma unroll
    for (int mi = 0; mi < 2; mi++) {
        const int gm0 = bm + wm + mi * 16 + (lane >> 2);
        #pragma unroll
        for (int j = 0; j < 4; j++) {
            const int col = wn + j * 8 + (lane & 3) * 2;
            float v0 = acc[mi][j][0], v1 = acc[mi][j][1];
            float v2 = acc[mi][j][2], v3 = acc[mi][j][3];
            if (y == 0) {
                long b0 = ((long)z * SEQ + gm0) * HD + col;
                *(uint32_t*)(Qh_g + b0) = pack_f16x2(v0 * 0.125f, v1 * 0.125f);
                *(uint32_t*)(Qh_g + b0 + 8L * HD) = pack_f16x2(v2 * 0.125f, v3 * 0.125f);
            } else if (y == 1) {
                long b0 = ((long)z * SEQ + gm0) * HD + col;
                write_split2(Khi + b0, Klo + b0, v0, v1);
                long b1 = b0 + 8L * HD;
                write_split2(Khi + b1, Klo + b1, v2, v3);
            } else {
                long t0 = ((long)z * HD + col) * SEQ + gm0;
                Vt[t0]           = __float2half_rn(v0);
                Vt[t0 + SEQ]     = __float2half_rn(v1);
                Vt[t0 + 8]       = __float2half_rn(v2);
                Vt[t0 + SEQ + 8] = __float2half_rn(v3);
            }
        }
    }
}

// ---------------------------------------------------------------------------
// Output projection: out[4096,512] = Hcat[4096,512] * W_O[512,512]^T (fp32)
// ---------------------------------------------------------------------------
__global__ __launch_bounds__(256) void gemm_out(
    const float* __restrict__ A, const float* __restrict__ W,
    float* __restrict__ C)
{
    __shared__ __half Ah[128 * G_LDA];
    __shared__ __half Bh[64 * G_LDA], Bl[64 * G_LDA];

    const int tid = threadIdx.x, wid = tid >> 5, lane = tid & 31;
    const int bm = blockIdx.x * 128, bn = blockIdx.y * 64;
    const float* B = W + (long)bn * FIN;
    const int wm = (wid & 3) * 32, wn = (wid >> 2) * 32;

    float acc[2][4][4] = {};
    float4 pa[4], pb[2];
    GEMM_PREFETCH(A, B, FIN, 0);

    for (int k0 = 0; k0 < FIN; k0 += 32) {
        __syncthreads();
        GEMM_STORE_SMEM();
        __syncthreads();
        if (k0 + 32 < FIN) GEMM_PREFETCH(A, B, FIN, k0 + 32);
        GEMM_MMA_BLOCK();
    }

    #pragma unroll
    for (int mi = 0; mi < 2; mi++) {
        const int gm0 = bm + wm + mi * 16 + (lane >> 2);
        #pragma unroll
        for (int j = 0; j < 4; j++) {
            const int col = bn + wn + j * 8 + (lane & 3) * 2;
            *(float2*)(C + (long)gm0 * FOUT + col) =
                make_float2(acc[mi][j][0], acc[mi][j][1]);
            *(float2*)(C + (long)(gm0 + 8) * FOUT + col) =
                make_float2(acc[mi][j][2], acc[mi][j][3]);
        }
    }
}

// ---------------------------------------------------------------------------
// HMMA flash attention. BQ=64, 128 threads, 2 CTAs/SM (R7 structure).
// S = Qh*(Kh+Kl) 2-term; PV = Ph*Vh 1-term. cp.async double-buffered.
// Mask via streaming loads (evict-first) to keep K/V L2-resident.
// ---------------------------------------------------------------------------
#define ATT_LDA 72
#define ROWB    144                    // bytes per smem row
#define HALF_A  9216                   // 64 rows * 144
#define K_STG   (2 * HALF_A)           // K hi+lo per stage = 18432
#define V_STG   HALF_A                 // V single per stage = 9216
#define OFF_K   HALF_A                 // after Q
#define OFF_V   (OFF_K + 2 * K_STG)
#define ATT_SMEM (OFF_V + 2 * V_STG)   // 64512 bytes

__global__ __launch_bounds__(128, 2) void attn_mma(
    const __half* __restrict__ Qh_g,
    const __half* __restrict__ Khi, const __half* __restrict__ Klo,
    const __half* __restrict__ Vt,
    const int* __restrict__ mask, float* __restrict__ Hcat)
{
    extern __shared__ char smc[];
    const uint32_t sb = smem_u32(smc);
    __half* Qs = (__half*)smc;

    const int tid = threadIdx.x, wid = tid >> 5, lane = tid & 31;
    const int h = blockIdx.y, q0 = blockIdx.x * 64;
    const long hS = (long)h * SEQ;

    // cp.async mapping: 128 threads, thread (rr, cc): rows rr+16k, 16B chunk cc
    const int rr = (tid >> 3) & 15;   // 0..15
    const int cc = tid & 7;
    const __half* pKh = Khi + (hS + rr) * HD + cc * 8;
    const __half* pKl = Klo + (hS + rr) * HD + cc * 8;
    const __half* pVh = Vt + ((long)h * HD + rr) * SEQ + cc * 8;
    const uint32_t sKf = sb + OFF_K + rr * ROWB + cc * 16;
    const uint32_t sVf = sb + OFF_V + rr * ROWB + cc * 16;

#define FILL_STAGE(kt_)                                                        \
    do {                                                                       \
        uint32_t k0s = sKf + ((kt_) & 1) * K_STG;                              \
        uint32_t v0s = sVf + ((kt_) & 1) * V_STG;                              \
        long ko = (long)(kt_) * 64;                                            \
        _Pragma("unroll")                                                      \
        for (int kq = 0; kq < 4; kq++) {                                       \
            cp16(k0s + kq * 16 * ROWB,          pKh + (ko + kq * 16) * HD);    \
            cp16(k0s + kq * 16 * ROWB + HALF_A, pKl + (ko + kq * 16) * HD);    \
            cp16(v0s + kq * 16 * ROWB,          pVh + (long)kq * 16 * SEQ + ko);\
        }                                                                      \
        CP_COMMIT();                                                           \
    } while (0)

    // Load Q tile (persist all iterations)
    #pragma unroll
    for (int it = 0; it < 4; it++) {
        int i = tid + it * 128;
        int r = i >> 3, c = i & 7;
        *(uint4*)(Qs + r * ATT_LDA + c * 8) =
            *(const uint4*)(Qh_g + (hS + q0 + r) * HD + c * 8);
    }
    FILL_STAGE(0);
    __syncthreads();

    // Q fragments -> registers
    uint32_t qh[4][4];
    {
        const int r = wid * 16 + (lane & 15);
        #pragma unroll
        for (int kc = 0; kc < 4; kc++) {
            const int col = kc * 16 + ((lane >> 4) << 3);
            ldsm_x4(qh[kc], smem_u32(Qs + r * ATT_LDA + col));
        }
    }

    float o[8][4] = {};
    float l0 = 0.f, l1 = 0.f;
    const int r0 = q0 + wid * 16 + (lane >> 2);
    const int colb = (lane & 3) * 2;
    const long mbase = (hS + r0) * SEQ;

    for (int kt = 0; kt < SEQ / 64; kt++) {
        if (kt) __syncthreads();
        if (kt + 1 < SEQ / 64) { FILL_STAGE(kt + 1); CP_WAIT(1); }
        else                   { CP_WAIT(0); }
        __syncthreads();

        const uint32_t kbK = sb + OFF_K + (kt & 1) * K_STG;
        const uint32_t kbV = sb + OFF_V + (kt & 1) * V_STG;

        // mask loads (streaming; hidden under S chain)
        int2 mv0[8], mv1[8];
        #pragma unroll
        for (int j = 0; j < 8; j++) {
            mv0[j] = ldcs2(mask + mbase + kt * 64 + j * 8 + colb);
            mv1[j] = ldcs2(mask + mbase + 8L * SEQ + kt * 64 + j * 8 + colb);
        }

        // S = Qh * (Kh + Kl)  (2-term)
        float s[8][4] = {};
        #pragma unroll
        for (int kc = 0; kc < 4; kc++) {
            uint32_t kbh[4][4], kbl[4][4];
            const int brow = ((lane >> 4) << 3) + (lane & 7);
            const int bcol = (kc * 16 + (((lane >> 3) & 1) << 3)) * 2;
            #pragma unroll
            for (int jp = 0; jp < 4; jp++) {
                ldsm_x4(kbh[jp], kbK + (jp * 16 + brow) * ROWB + bcol);
                ldsm_x4(kbl[jp], kbK + HALF_A + (jp * 16 + brow) * ROWB + bcol);
            }
            #pragma unroll
            for (int jp = 0; jp < 4; jp++) {
                mma_f16(s[2 * jp],     qh[kc], &kbh[jp][0]);
                mma_f16(s[2 * jp],     qh[kc], &kbl[jp][0]);
                mma_f16(s[2 * jp + 1], qh[kc], &kbh[jp][2]);
                mma_f16(s[2 * jp + 1], qh[kc], &kbl[jp][2]);
            }
        }

        // mask + exp (no rescale; Q pre-scaled so s is the exponent arg)
        const float CE = 1.44269504f;   // log2(e)
        #pragma unroll
        for (int j = 0; j < 8; j++) {
            float p0 = mv0[j].x ? ex2f(s[j][0] * CE) : 0.f;
            float p1 = mv0[j].y ? ex2f(s[j][1] * CE) : 0.f;
            float p2 = mv1[j].x ? ex2f(s[j][2] * CE) : 0.f;
            float p3 = mv1[j].y ? ex2f(s[j][3] * CE) : 0.f;
            l0 += p0 + p1;
            l1 += p2 + p3;
            s[j][0] = p0; s[j][1] = p1; s[j][2] = p2; s[j][3] = p3;
        }

        // Repack P C-frags -> A-frags (fp16)
        uint32_t ph[4][4];
        #pragma unroll
        for (int kc = 0; kc < 4; kc++) {
            #pragma unroll
            for (int u = 0; u < 2; u++) {
                const int j = 2 * kc + u;
                ph[kc][2 * u]     = pack_f16x2(s[j][0], s[j][1]);
                ph[kc][2 * u + 1] = pack_f16x2(s[j][2], s[j][3]);
            }
        }

        // O += Ph * Vh  (1-term)
        #pragma unroll
        for (int kc = 0; kc < 4; kc++) {
            uint32_t vbh[4][4];
            const int brow = ((lane >> 4) << 3) + (lane & 7);
            const int bcol = (kc * 16 + (((lane >> 3) & 1) << 3)) * 2;
            #pragma unroll
            for (int jp = 0; jp < 4; jp++)
                ldsm_x4(vbh[jp], kbV + (jp * 16 + brow) * ROWB + bcol);
            #pragma unroll
            for (int jp = 0; jp < 4; jp++) {
                mma_f16(o[2 * jp],     ph[kc], &vbh[jp][0]);
                mma_f16(o[2 * jp + 1], ph[kc], &vbh[jp][2]);
            }
        }
    }

    // Row-sum reduce across the quad, normalize, write Hcat
    l0 += __shfl_xor_sync(0xffffffffu, l0, 1);
    l0 += __shfl_xor_sync(0xffffffffu, l0, 2);
    l1 += __shfl_xor_sync(0xffffffffu, l1, 1);
    l1 += __shfl_xor_sync(0xffffffffu, l1, 2);
    const float i0 = 1.f / l0, i1 = 1.f / l1;
    #pragma unroll
    for (int j = 0; j < 8; j++) {
        const int colg = h * HD + j * 8 + colb;
        *(float2*)(Hcat + (long)r0 * (HEADS * HD) + colg) =
            make_float2(o[j][0] * i0, o[j][1] * i0);
        *(float2*)(Hcat + (long)(r0 + 8) * (HEADS * HD) + colg) =
            make_float2(o[j][2] * i1, o[j][3] * i1);
    }
}

// ---------------------------------------------------------------------------
extern "C" void kernel_launch(void* const* d_in, const int* in_sizes, int n_in,
                              void* d_out, int out_size)
{
    const float* X    = (const float*)d_in[0];
    const int*   mask = (const int*)  d_in[1];
    const float* W_Q  = (const float*)d_in[2];
    const float* W_K  = (const float*)d_in[3];
    const float* W_V  = (const float*)d_in[4];
    const float* W_O  = (const float*)d_in[5];
    float* out = (float*)d_out;

    __half *Qh_g, *Khi, *Klo, *Vt;
    float* Hc;
    cudaGetSymbolAddress((void**)&Qh_g, g_Qh);
    cudaGetSymbolAddress((void**)&Khi,  g_Khi);
    cudaGetSymbolAddress((void**)&Klo,  g_Klo);
    cudaGetSymbolAddress((void**)&Vt,   g_Vt);
    cudaGetSymbolAddress((void**)&Hc,   g_Hcat);

    // Fused Q/K/V projections
    dim3 gProj(SEQ / 128, 3, HEADS);
    proj_qkv<<<gProj, 256>>>(X, W_Q, W_K, W_V, Qh_g, Khi, Klo, Vt);

    // Attention (BQ=64, 2 CTAs/SM)
    cudaFuncSetAttribute(attn_mma,
                         cudaFuncAttributeMaxDynamicSharedMemorySize, ATT_SMEM);
    dim3 gAttn(SEQ / 64, HEADS);
    attn_mma<<<gAttn, 128, ATT_SMEM>>>(Qh_g, Khi, Klo, Vt, mask, Hc);

    // Output projection
    dim3 gOut(SEQ / 128, FOUT / 64);
    gemm_out<<<gOut, 256>>>(Hc, W_O, out);
}